// round 3
// baseline (speedup 1.0000x reference)
#include <cuda_runtime.h>
#include <math.h>

typedef unsigned long long u64;

#define NN   32
#define CCH  64
#define TTT  400
#define VVV  27
#define VP   28
#define SSS  2
#define TVC  (TTT*VVV)       // 10800
#define CTV  (CCH*TVC)       // 691200
#define TV28 (TTT*VP)        // 11200
#define CTV28 (CCH*TV28)     // 716800
#define LEAK 0.1f
#define EPSB 1e-5f
#define KSP  25
#define TB   16

#define BM   112             // m-tile (4 t x 28 padded v)
#define THR  224             // (28 m-groups) x (8 oc-groups)
#define WS   68              // padded weight-row stride (floats), 16B-aligned
#define PS   68              // padded P-row stride

// scratch (static device globals — allocation-free rule)
__device__ float g_buf1[NN*CCH*TV28];   // qk, later y2
__device__ float g_buf2[NN*CCH*TV28];   // y3
__device__ float g_att_part[KSP*NN*SSS*VVV*VVV];
__device__ float g_att[NN*SSS*VVV*VVV];

// ---- packed fp32x2 helpers ----
__device__ __forceinline__ u64 ffma2(u64 a, u64 b, u64 c) {
    u64 d; asm("fma.rn.f32x2 %0, %1, %2, %3;" : "=l"(d) : "l"(a), "l"(b), "l"(c));
    return d;
}
__device__ __forceinline__ u64 bcast2(float w) {
    u64 d; asm("mov.b64 %0, {%1, %1};" : "=l"(d) : "r"(__float_as_uint(w)));
    return d;
}
__device__ __forceinline__ float2 unpk(u64 a) {
    float2 r; asm("mov.b64 {%0, %1}, %2;" : "=f"(r.x), "=f"(r.y) : "l"(a));
    return r;
}

// one outer-product k-step: xr[112] row, wr[64+] row, ACC[4][4] (oc-paired)
#define GEMM_STEP(ACC, xr, wr) do {                                         \
    float4 _xf = *(const float4*)((xr) + tm4);                              \
    ulonglong2 _wa = *(const ulonglong2*)((wr) + tn8);                      \
    ulonglong2 _wb = *(const ulonglong2*)((wr) + tn8 + 4);                  \
    u64 _x0 = bcast2(_xf.x), _x1 = bcast2(_xf.y);                           \
    u64 _x2 = bcast2(_xf.z), _x3 = bcast2(_xf.w);                           \
    ACC[0][0]=ffma2(_x0,_wa.x,ACC[0][0]); ACC[0][1]=ffma2(_x0,_wa.y,ACC[0][1]); \
    ACC[0][2]=ffma2(_x0,_wb.x,ACC[0][2]); ACC[0][3]=ffma2(_x0,_wb.y,ACC[0][3]); \
    ACC[1][0]=ffma2(_x1,_wa.x,ACC[1][0]); ACC[1][1]=ffma2(_x1,_wa.y,ACC[1][1]); \
    ACC[1][2]=ffma2(_x1,_wb.x,ACC[1][2]); ACC[1][3]=ffma2(_x1,_wb.y,ACC[1][3]); \
    ACC[2][0]=ffma2(_x2,_wa.x,ACC[2][0]); ACC[2][1]=ffma2(_x2,_wa.y,ACC[2][1]); \
    ACC[2][2]=ffma2(_x2,_wb.x,ACC[2][2]); ACC[2][3]=ffma2(_x2,_wb.y,ACC[2][3]); \
    ACC[3][0]=ffma2(_x3,_wa.x,ACC[3][0]); ACC[3][1]=ffma2(_x3,_wa.y,ACC[3][1]); \
    ACC[3][2]=ffma2(_x3,_wb.x,ACC[3][2]); ACC[3][3]=ffma2(_x3,_wb.y,ACC[3][3]); \
} while(0)

#define UNPACK_ACC(ACC, VA) do {                                            \
    _Pragma("unroll") for (int _mi = 0; _mi < 4; _mi++)                     \
    _Pragma("unroll") for (int _nj = 0; _nj < 4; _nj++) {                   \
        float2 _p = unpk(ACC[_mi][_nj]);                                    \
        VA[_mi][2*_nj] = _p.x; VA[_mi][2*_nj+1] = _p.y; }                   \
} while(0)

// stage x-style tensor (unpadded global rows of 108) into padded sX[64][112]
__device__ __forceinline__ void stage_x_pad(float* sX, const float* gbase,
                                            int tid) {
    for (int i = tid; i < 64*27; i += THR) {
        int c = i / 27, q = i - c*27;
        float4 xv = *(const float4*)&gbase[c*TVC + 4*q];
        int p = 4*q;
#pragma unroll
        for (int e = 0; e < 4; e++) {
            int pp = p + e, tq = pp/27, v = pp - tq*27;
            sX[c*BM + tq*VP + v] = ((const float*)&xv)[e];
        }
    }
    for (int i = tid; i < 256; i += THR) {
        int c = i >> 2, tq = i & 3;
        sX[c*BM + tq*VP + 27] = 0.f;
    }
}

// ---------------------------------------------------------------------------
// K1: qk = W_in @ (x+pe) + b_in  -> padded g_buf1
// ---------------------------------------------------------------------------
__global__ __launch_bounds__(THR, 2) void k1_qk(const float* __restrict__ x,
                                                const float* __restrict__ pe,
                                                const float* __restrict__ Wi,
                                                const float* __restrict__ bi) {
    extern __shared__ float sm[];
    float* sX = sm;               // [64][112]
    float* sW = sm + 64*BM;       // [64][WS]
    int n = blockIdx.y, m0 = BM*blockIdx.x;
    int tid = threadIdx.x;
    int tm = tid % 28, tn = tid / 28;
    int tm4 = tm*4, tn8 = tn*8;
    // stage W: sW[c][o]
    for (int i = tid; i < 4096; i += THR) {
        int o = i >> 6, c = i & 63;
        sW[c*WS + o] = Wi[i];
    }
    // stage x+pe padded
    {
        const float* gx = x + n*CTV + (m0/VP)*27;
        const float* gp = pe + (m0/VP)*27;
        for (int i = tid; i < 64*27; i += THR) {
            int c = i / 27, q = i - c*27;
            float4 xv = *(const float4*)&gx[c*TVC + 4*q];
            float4 pv = *(const float4*)&gp[c*TVC + 4*q];
            float vals[4] = {xv.x+pv.x, xv.y+pv.y, xv.z+pv.z, xv.w+pv.w};
            int p = 4*q;
#pragma unroll
            for (int e = 0; e < 4; e++) {
                int pp = p + e, tq = pp/27, v = pp - tq*27;
                sX[c*BM + tq*VP + v] = vals[e];
            }
        }
        for (int i = tid; i < 256; i += THR) {
            int c = i >> 2, tq = i & 3;
            sX[c*BM + tq*VP + 27] = 0.f;
        }
    }
    __syncthreads();

    u64 acc[4][4];
#pragma unroll
    for (int a = 0; a < 4; a++)
#pragma unroll
        for (int b = 0; b < 4; b++) acc[a][b] = 0ull;
#pragma unroll 4
    for (int c = 0; c < 64; c++)
        GEMM_STEP(acc, &sX[c*BM], &sW[c*WS]);

    float va[4][8];
    UNPACK_ACC(acc, va);
    int oc0 = tn8;
#pragma unroll
    for (int l = 0; l < 8; l++) {
        float b = bi[oc0 + l];
        float4 o4 = make_float4(va[0][l]+b, va[1][l]+b, va[2][l]+b, va[3][l]+b);
        *(float4*)&g_buf1[n*CTV28 + (oc0+l)*TV28 + m0 + tm4] = o4;
    }
}

// ---------------------------------------------------------------------------
// K2: unchanged (cheap) — partial q.k reduction + tanh finalize
// ---------------------------------------------------------------------------
__global__ __launch_bounds__(96) void k2_part() {
    int ksp = blockIdx.x, s = blockIdx.y, n = blockIdx.z;
    __shared__ float sq[16*8*27], sk[16*8*27];
    int tid = threadIdx.x;
    int tu = (tid < 81) ? tid/9 : 0, tv = (tid < 81) ? tid%9 : 0;
    int u0 = 3*tu, v0 = 3*tv;
    float a00=0,a01=0,a02=0,a10=0,a11=0,a12=0,a20=0,a21=0,a22=0;
    for (int ch = 0; ch < 2; ch++) {
        int tbase = ksp*TB + ch*8;
        for (int i = tid; i < 3456; i += 96) {
            int u = i%27; int t8 = (i/27)&7; int c = i/216;
            int gq = n*CTV28 + (s*16 + c)*TV28 + (tbase + t8)*VP + u;
            sq[i] = g_buf1[gq];
            sk[i] = g_buf1[gq + 32*TV28];
        }
        __syncthreads();
        if (tid < 81) {
#pragma unroll
            for (int c = 0; c < 16; c++) {
#pragma unroll
                for (int t8 = 0; t8 < 8; t8++) {
                    const float* qr = &sq[(c*8+t8)*27];
                    const float* kr = &sk[(c*8+t8)*27];
                    float q0=qr[u0],q1=qr[u0+1],q2=qr[u0+2];
                    float k0=kr[v0],k1=kr[v0+1],k2=kr[v0+2];
                    a00+=q0*k0; a01+=q0*k1; a02+=q0*k2;
                    a10+=q1*k0; a11+=q1*k1; a12+=q1*k2;
                    a20+=q2*k0; a21+=q2*k1; a22+=q2*k2;
                }
            }
        }
        __syncthreads();
    }
    if (tid < 81) {
        float* dst = &g_att_part[((ksp*NN + n)*SSS + s)*729];
        dst[(u0+0)*27+v0+0]=a00; dst[(u0+0)*27+v0+1]=a01; dst[(u0+0)*27+v0+2]=a02;
        dst[(u0+1)*27+v0+0]=a10; dst[(u0+1)*27+v0+1]=a11; dst[(u0+1)*27+v0+2]=a12;
        dst[(u0+2)*27+v0+0]=a20; dst[(u0+2)*27+v0+1]=a21; dst[(u0+2)*27+v0+2]=a22;
    }
}

__global__ void k2_fin(const float* __restrict__ alphas, const float* __restrict__ att0) {
    int i = blockIdx.x*256 + threadIdx.x;
    if (i >= NN*SSS*729) return;
    float acc = 0.f;
#pragma unroll
    for (int sp = 0; sp < KSP; sp++) acc += g_att_part[sp*(NN*SSS*729) + i];
    int r = i % (SSS*729); int s = r/729; int uv = r%729;
    g_att[i] = tanhf(acc * (1.f/6400.f)) * alphas[s] + att0[s*729 + uv];
}

// ---------------------------------------------------------------------------
// K3a: per s: P = W_out_s @ x (to smem), y += P @ A_s ; then
//      y2 = lrelu(x + BN(y + b_out)) -> padded g_buf1
// ---------------------------------------------------------------------------
#define K3A_SMEM (64*BM + 128*WS + BM*PS + 2*28*28)
__global__ __launch_bounds__(THR, 2) void k3a(
    const float* __restrict__ x,
    const float* __restrict__ Wo, const float* __restrict__ bo,
    const float* __restrict__ go, const float* __restrict__ beo,
    const float* __restrict__ mo, const float* __restrict__ vo) {
    extern __shared__ float sm[];
    float* sX = sm;                         // [64][112]  (x)
    float* sW = sm + 64*BM;                 // [128][WS]
    float* sP = sm + 64*BM + 128*WS;        // [112][PS]
    float* sA = sm + 64*BM + 128*WS + BM*PS;// [2][28][28]
    int n = blockIdx.y, m0 = BM*blockIdx.x;
    int tid = threadIdx.x;
    int tm = tid % 28, tn = tid / 28;
    int tm4 = tm*4, tn8 = tn*8;
    int t_loc = tm4 / VP;
    int v0 = tm4 - t_loc*VP;

    for (int i = tid; i < 8192; i += THR) {
        int o = i >> 7, k = i & 127;
        sW[k*WS + o] = Wo[i];
    }
    for (int i = tid; i < 2*28*28; i += THR) sA[i] = 0.f;
    __syncthreads();   // before sA fill (zero visible)
    for (int i = tid; i < 1458; i += THR) {
        int s = i / 729, r = i - s*729;
        int u = r / 27, v = r - u*27;
        sA[(s*28+u)*28 + v] = g_att[(n*SSS+s)*729 + r];
    }
    stage_x_pad(sX, x + n*CTV + (m0/VP)*27, tid);
    __syncthreads();

    u64 accY[4][4];
#pragma unroll
    for (int a = 0; a < 4; a++)
#pragma unroll
        for (int b = 0; b < 4; b++) accY[a][b] = 0ull;

    for (int s = 0; s < 2; s++) {
        u64 accP[4][4];
#pragma unroll
        for (int a = 0; a < 4; a++)
#pragma unroll
            for (int b = 0; b < 4; b++) accP[a][b] = 0ull;
#pragma unroll 4
        for (int c = 0; c < 64; c++)
            GEMM_STEP(accP, &sX[c*BM], &sW[(s*64+c)*WS]);
        __syncthreads();   // prior phase-2 readers done before overwrite
#pragma unroll
        for (int mi = 0; mi < 4; mi++) {
            int row = tm4 + mi;
            *(ulonglong2*)&sP[row*PS + tn8]     = make_ulonglong2(accP[mi][0], accP[mi][1]);
            *(ulonglong2*)&sP[row*PS + tn8 + 4] = make_ulonglong2(accP[mi][2], accP[mi][3]);
        }
        __syncthreads();
        // y += P @ A_s  (K = 27 over u)
#pragma unroll 3
        for (int u = 0; u < 27; u++) {
            float4 af = *(const float4*)&sA[(s*28+u)*28 + v0];
            const float* pr = &sP[(t_loc*VP + u)*PS + tn8];
            ulonglong2 pa = *(const ulonglong2*)pr;
            ulonglong2 pb = *(const ulonglong2*)(pr + 4);
            u64 a0 = bcast2(af.x), a1 = bcast2(af.y), a2 = bcast2(af.z), a3 = bcast2(af.w);
            accY[0][0]=ffma2(a0,pa.x,accY[0][0]); accY[0][1]=ffma2(a0,pa.y,accY[0][1]);
            accY[0][2]=ffma2(a0,pb.x,accY[0][2]); accY[0][3]=ffma2(a0,pb.y,accY[0][3]);
            accY[1][0]=ffma2(a1,pa.x,accY[1][0]); accY[1][1]=ffma2(a1,pa.y,accY[1][1]);
            accY[1][2]=ffma2(a1,pb.x,accY[1][2]); accY[1][3]=ffma2(a1,pb.y,accY[1][3]);
            accY[2][0]=ffma2(a2,pa.x,accY[2][0]); accY[2][1]=ffma2(a2,pa.y,accY[2][1]);
            accY[2][2]=ffma2(a2,pb.x,accY[2][2]); accY[2][3]=ffma2(a2,pb.y,accY[2][3]);
            accY[3][0]=ffma2(a3,pa.x,accY[3][0]); accY[3][1]=ffma2(a3,pa.y,accY[3][1]);
            accY[3][2]=ffma2(a3,pb.x,accY[3][2]); accY[3][3]=ffma2(a3,pb.y,accY[3][3]);
        }
    }

    float va[4][8];
    UNPACK_ACC(accY, va);
    int oc0 = tn8;
#pragma unroll
    for (int l = 0; l < 8; l++) {
        int oc = oc0 + l;
        float sc = go[oc]*rsqrtf(vo[oc]+EPSB);
        float bb = bo[oc], mm = mo[oc], be = beo[oc];
        float o4[4];
#pragma unroll
        for (int mi = 0; mi < 4; mi++) {
            float y1 = va[mi][l] + bb;
            float t  = sX[oc*BM + tm4 + mi] + (y1 - mm)*sc + be;
            o4[mi] = (t >= 0.f) ? t : LEAK*t;
        }
        *(float4*)&g_buf1[n*CTV28 + oc*TV28 + m0 + tm4] =
            make_float4(o4[0], o4[1], o4[2], o4[3]);
    }
}

// ---------------------------------------------------------------------------
// K3b: y3 = lrelu(x + BN(W_ff @ y2 + b_ff)) -> padded g_buf2
// ---------------------------------------------------------------------------
__global__ __launch_bounds__(THR, 2) void k3b(
    const float* __restrict__ x,
    const float* __restrict__ Wf, const float* __restrict__ bf,
    const float* __restrict__ gf, const float* __restrict__ bef,
    const float* __restrict__ mf, const float* __restrict__ vf) {
    extern __shared__ float sm[];
    float* sX = sm;               // [64][112] (y2, padded)
    float* sW = sm + 64*BM;       // [64][WS]
    int n = blockIdx.y, m0 = BM*blockIdx.x;
    int tid = threadIdx.x;
    int tm = tid % 28, tn = tid / 28;
    int tm4 = tm*4, tn8 = tn*8;
    for (int i = tid; i < 4096; i += THR) {
        int o = i >> 6, c = i & 63;
        sW[c*WS + o] = Wf[i];
    }
    for (int i = tid; i < 64*28; i += THR) {
        int c = i / 28, q = i - c*28;
        ((float4*)&sX[c*BM])[q] =
            ((const float4*)&g_buf1[n*CTV28 + c*TV28 + m0])[q];
    }
    __syncthreads();

    u64 acc[4][4];
#pragma unroll
    for (int a = 0; a < 4; a++)
#pragma unroll
        for (int b = 0; b < 4; b++) acc[a][b] = 0ull;
#pragma unroll 4
    for (int c = 0; c < 64; c++)
        GEMM_STEP(acc, &sX[c*BM], &sW[c*WS]);

    float va[4][8];
    UNPACK_ACC(acc, va);
    int oc0 = tn8;
    int tg = (m0 + tm4) / VP;          // global t for this quad
    int vg = (m0 + tm4) - tg*VP;       // v of first element
#pragma unroll
    for (int l = 0; l < 8; l++) {
        int oc = oc0 + l;
        float sc = gf[oc]*rsqrtf(vf[oc]+EPSB);
        float bb = bf[oc], mm = mf[oc], be = bef[oc];
        float o4[4];
#pragma unroll
        for (int mi = 0; mi < 4; mi++) {
            int v = vg + mi;
            float xr = (v < 27) ? x[n*CTV + oc*TVC + tg*27 + v] : 0.f;
            float yf = va[mi][l] + bb;
            float t  = xr + (yf - mm)*sc + be;
            o4[mi] = (t >= 0.f) ? t : LEAK*t;
        }
        *(float4*)&g_buf2[n*CTV28 + oc*TV28 + m0 + tm4] =
            make_float4(o4[0], o4[1], o4[2], o4[3]);
    }
}

// ---------------------------------------------------------------------------
// K4: z = BN(tconv3(y3) + b_t); out = lrelu(y3 + z) -> d_out (unpadded)
// ---------------------------------------------------------------------------
#define K4_SMEM (64*BM + 192*WS)
__global__ __launch_bounds__(THR, 2) void k4_tconv(
    const float* __restrict__ Wt, const float* __restrict__ bt,
    const float* __restrict__ gt, const float* __restrict__ bet,
    const float* __restrict__ mt, const float* __restrict__ vt,
    float* __restrict__ out) {
    extern __shared__ float sm[];
    float* sX = sm;               // [64][112], restaged per dt
    float* sW = sm + 64*BM;       // [192][WS], k = dt*64 + c
    int n = blockIdx.y, m0 = BM*blockIdx.x;
    int tid = threadIdx.x;
    int tm = tid % 28, tn = tid / 28;
    int tm4 = tm*4, tn8 = tn*8;
    for (int i = tid; i < 12288; i += THR) {
        int o = i & 63, c = (i >> 6) & 63, kt = i >> 12;
        sW[(kt*64 + c)*WS + o] = Wt[(o*64 + c)*3 + kt];
    }
    u64 acc[4][4];
#pragma unroll
    for (int a = 0; a < 4; a++)
#pragma unroll
        for (int b = 0; b < 4; b++) acc[a][b] = 0ull;

    const int order[3] = {0, 2, 1};     // dt=1 last -> residual resident
    for (int ci = 0; ci < 3; ci++) {
        int dt = order[ci];
        if (ci > 0) __syncthreads();
        for (int i = tid; i < 64*28; i += THR) {
            int c = i / 28, q = i - c*28;
            int s_off = m0 + (dt-1)*VP + 4*q;
            float4 val = make_float4(0.f, 0.f, 0.f, 0.f);
            if (s_off >= 0 && s_off < TV28)
                val = *(const float4*)&g_buf2[n*CTV28 + c*TV28 + s_off];
            ((float4*)&sX[c*BM])[q] = val;
        }
        __syncthreads();
#pragma unroll 4
        for (int c = 0; c < 64; c++)
            GEMM_STEP(acc, &sX[c*BM], &sW[(dt*64+c)*WS]);
    }

    float va[4][8];
    UNPACK_ACC(acc, va);
    int oc0 = tn8;
    int tg = (m0 + tm4) / VP;
    int vg = (m0 + tm4) - tg*VP;
#pragma unroll
    for (int l = 0; l < 8; l++) {
        int oc = oc0 + l;
        float sc = gt[oc]*rsqrtf(vt[oc]+EPSB);
        float bb = bt[oc], mm = mt[oc], be = bet[oc];
#pragma unroll
        for (int mi = 0; mi < 4; mi++) {
            int v = vg + mi;
            if (v < 27) {
                float z = (va[mi][l] + bb - mm)*sc + be;
                float r = sX[oc*BM + tm4 + mi] + z;   // y3 (dt=1 resident)
                out[n*CTV + oc*TVC + tg*27 + v] = (r >= 0.f) ? r : LEAK*r;
            }
        }
    }
}

// ---------------------------------------------------------------------------
extern "C" void kernel_launch(void* const* d_in, const int* in_sizes, int n_in,
                              void* d_out, int out_size) {
    const float* x      = (const float*)d_in[0];
    const float* pe     = (const float*)d_in[1];
    const float* W_in   = (const float*)d_in[2];
    const float* b_in   = (const float*)d_in[3];
    const float* alphas = (const float*)d_in[4];
    const float* att0   = (const float*)d_in[5];
    const float* W_out  = (const float*)d_in[6];
    const float* b_out  = (const float*)d_in[7];
    const float* g_out  = (const float*)d_in[8];
    const float* be_out = (const float*)d_in[9];
    const float* m_out  = (const float*)d_in[10];
    const float* v_out  = (const float*)d_in[11];
    const float* W_ff   = (const float*)d_in[12];
    const float* b_ff   = (const float*)d_in[13];
    const float* g_ff   = (const float*)d_in[14];
    const float* be_ff  = (const float*)d_in[15];
    const float* m_ff   = (const float*)d_in[16];
    const float* v_ff   = (const float*)d_in[17];
    const float* W_t    = (const float*)d_in[18];
    const float* b_t    = (const float*)d_in[19];
    const float* g_t    = (const float*)d_in[20];
    const float* be_t   = (const float*)d_in[21];
    const float* m_t    = (const float*)d_in[22];
    const float* v_t    = (const float*)d_in[23];
    float* out = (float*)d_out;

    int smem_k1  = (64*BM + 64*WS)*4;
    int smem_k3a = K3A_SMEM*4;
    int smem_k3b = (64*BM + 64*WS)*4;
    int smem_k4  = K4_SMEM*4;
    cudaFuncSetAttribute(k1_qk, cudaFuncAttributeMaxDynamicSharedMemorySize, smem_k1);
    cudaFuncSetAttribute(k3a,   cudaFuncAttributeMaxDynamicSharedMemorySize, smem_k3a);
    cudaFuncSetAttribute(k3b,   cudaFuncAttributeMaxDynamicSharedMemorySize, smem_k3b);
    cudaFuncSetAttribute(k4_tconv, cudaFuncAttributeMaxDynamicSharedMemorySize, smem_k4);

    dim3 grid(100, 32);
    k1_qk<<<grid, THR, smem_k1>>>(x, pe, W_in, b_in);
    k2_part<<<dim3(KSP, 2, 32), 96>>>();
    k2_fin<<<(NN*SSS*729 + 255)/256, 256>>>(alphas, att0);
    k3a<<<grid, THR, smem_k3a>>>(
        x, W_out, b_out, g_out, be_out, m_out, v_out);
    k3b<<<grid, THR, smem_k3b>>>(
        x, W_ff, b_ff, g_ff, be_ff, m_ff, v_ff);
    k4_tconv<<<grid, THR, smem_k4>>>(
        W_t, b_t, g_t, be_t, m_t, v_t, out);
}